// round 11
// baseline (speedup 1.0000x reference)
#include <cuda_runtime.h>
#include <cstdint>

#define CCH 256
#define HH 256
#define WW 256
#define PLANE (HH * WW)
#define TH 8
#define TW 32
#define HALO_ROWS 14              // TH + 6
#define HALO_W2 20                // staged float2 per row (40 floats)
#define HALO_N2 (HALO_ROWS * HALO_W2)  // 280 float2 per channel slab
#define SMW 44                    // y slab row stride in floats (conflict-free padding)
#define SMW2 (SMW / 2)            // 22 float2 stride
#define SLAB (HALO_ROWS * SMW)    // 616 floats per y slab
#define XROW 36                   // x slab row stride in floats (conflict-free padding)
#define XSLAB (TH * XROW)         // 288 floats per x slab
#define CPB 4                     // channels per barrier
#define NGRP (CCH / CPB)          // 64 groups
#define NSLOT 2                   // ceil(280 / 256) y staging slots per thread
#define W7SLOT 9                  // ceil(280 / 32) halo slots per warp-7 lane
#define NTHREADS 256
#define EPSF 1e-12f

__device__ __forceinline__ unsigned smem_u32(const void* p) {
    return (unsigned)__cvta_generic_to_shared(p);
}
__device__ __forceinline__ void cp_async8(unsigned dst, const void* src, unsigned sz) {
    asm volatile("cp.async.ca.shared.global [%0], [%1], 8, %2;\n"
                 :: "r"(dst), "l"(src), "r"(sz));
}
__device__ __forceinline__ void cp_async16(unsigned dst, const void* src) {
    asm volatile("cp.async.ca.shared.global [%0], [%1], 16;\n"
                 :: "r"(dst), "l"(src));
}
__device__ __forceinline__ void cp_commit() {
    asm volatile("cp.async.commit_group;\n");
}
__device__ __forceinline__ void cp_wait0() {
    asm volatile("cp.async.wait_group 0;\n");
}

__global__ __launch_bounds__(NTHREADS, 2)
void corr_kernel(const float* __restrict__ x,
                 const float* __restrict__ y,
                 float* __restrict__ out)
{
    __shared__ __align__(16) float sy[2][CPB][SLAB];
    __shared__ __align__(16) float sx[2][CPB][XSLAB];

    const int tid  = threadIdx.x;
    const int lane = tid & 31;
    const int tx   = tid & 3;          // 0..3, each owns 8 w-pixels
    const int ty   = (tid >> 2) & 7;   // 0..7
    const int grp  = tid >> 5;         // warp id: 0..6 compute offsets, 7 = norm warp
    const bool comp = (grp < 7);
    const int b   = blockIdx.z;
    const int h0  = blockIdx.y * TH;
    const int w0  = blockIdx.x * TW;
    const int h   = h0 + ty;

    // ---- y staging slots: halo gy in [h0-3, h0+10], gx in [w0-4, w0+35], even gx
    int      g2of[NSLOT];
    int      d2of[NSLOT];
    unsigned ssz[NSLOT];
    bool     wr[NSLOT];
    #pragma unroll
    for (int k = 0; k < NSLOT; k++) {
        int li = tid + k * NTHREADS;
        int r  = li / HALO_W2;
        int c2 = li - r * HALO_W2;
        int gy = h0 - 3 + r;
        int gx = w0 - 4 + 2 * c2;
        wr[k]  = li < HALO_N2;
        bool v = wr[k] && gy >= 0 && gy < HH && gx >= 0 && gx < WW;
        g2of[k] = v ? (gy * (WW / 2) + (gx >> 1)) : 0;
        d2of[k] = r * SMW2 + c2;
        ssz[k]  = v ? 8u : 0u;
    }

    // ---- x staging: threads 0..63 stage one float4 per channel
    const bool xstage = (tid < 64);
    const unsigned xdst = (unsigned)((tid >> 3) * (XROW * 4) + (tid & 7) * 16);
    const float* xsrc = x + (((size_t)b * CCH) * HH + h0 + (tid >> 3)) * WW
                          + w0 + (tid & 7) * 4;
    const float2* yc = reinterpret_cast<const float2*>(y) +
        (size_t)b * CCH * (PLANE / 2);

    // compute-warp accumulators
    float acc[7][8];
    #pragma unroll
    for (int j = 0; j < 7; j++)
        #pragma unroll
        for (int p = 0; p < 8; p++)
            acc[j][p] = 0.f;

    // norm-warp (warp 7) state
    float sxxw[8];
    #pragma unroll
    for (int p = 0; p < 8; p++) sxxw[p] = 0.f;
    float syyA[W7SLOT], syyB[W7SLOT];
    int   soff[W7SLOT];
    unsigned sv = 0;
    #pragma unroll
    for (int k = 0; k < W7SLOT; k++) {
        syyA[k] = 0.f; syyB[k] = 0.f;
        int s = lane + 32 * k;
        bool v = (!comp) && s < HALO_N2;
        soff[k] = v ? ((s / HALO_W2) * SMW2 + s % HALO_W2) : 0;
        if (v) sv |= 1u << k;
    }
    const int xwoff = (lane >> 2) * XROW + (lane & 3) * 8;

    // ---- prologue: stage group 0 (channels 0..3) into buffer 0
    #pragma unroll
    for (int cc = 0; cc < CPB; cc++) {
        unsigned dy = smem_u32(&sy[0][cc][0]);
        #pragma unroll
        for (int k = 0; k < NSLOT; k++)
            if (wr[k]) cp_async8(dy + (unsigned)d2of[k] * 8, yc + g2of[k], ssz[k]);
        yc += PLANE / 2;
        if (xstage)
            cp_async16(smem_u32(&sx[0][cc][0]) + xdst, xsrc + (size_t)cc * PLANE);
    }
    cp_commit();
    cp_wait0();
    __syncthreads();

    // ================= group loop: 64 iterations of 4 channels =================
    #pragma unroll 1
    for (int g = 0; g < NGRP; g++) {
        const int buf = g & 1;
        const bool pf = (g + 1 < NGRP);

        if (pf) {
            #pragma unroll
            for (int cc = 0; cc < CPB; cc++) {
                unsigned dy = smem_u32(&sy[buf ^ 1][cc][0]);
                #pragma unroll
                for (int k = 0; k < NSLOT; k++)
                    if (wr[k]) cp_async8(dy + (unsigned)d2of[k] * 8,
                                         yc + g2of[k], ssz[k]);
                yc += PLANE / 2;
                if (xstage)
                    cp_async16(smem_u32(&sx[buf ^ 1][cc][0]) + xdst,
                               xsrc + (size_t)((g + 1) * CPB + cc) * PLANE);
            }
            cp_commit();
        }

        // ---- process 4 channels; warp role hoisted OUTSIDE the channel loop
        if (comp) {
            const float* xr0 = &sx[buf][0][ty * XROW + tx * 8];
            const float* yr0 = &sy[buf][0][(ty + grp) * SMW + tx * 8];
            #pragma unroll
            for (int cc = 0; cc < CPB; cc++) {
                const float* xr = xr0 + cc * XSLAB;
                float4 xa = *reinterpret_cast<const float4*>(xr);
                float4 xb = *reinterpret_cast<const float4*>(xr + 4);
                float xv[8] = {xa.x, xa.y, xa.z, xa.w, xb.x, xb.y, xb.z, xb.w};

                const float* row = yr0 + cc * SLAB;
                float4 t0 = *reinterpret_cast<const float4*>(row);
                float4 t1 = *reinterpret_cast<const float4*>(row + 4);
                float4 t2 = *reinterpret_cast<const float4*>(row + 8);
                float4 t3 = *reinterpret_cast<const float4*>(row + 12);
                float yr[16] = {t0.x, t0.y, t0.z, t0.w, t1.x, t1.y, t1.z, t1.w,
                                t2.x, t2.y, t2.z, t2.w, t3.x, t3.y, t3.z, t3.w};
                #pragma unroll
                for (int j = 0; j < 7; j++)
                    #pragma unroll
                    for (int p = 0; p < 8; p++)
                        acc[j][p] = fmaf(xv[p], yr[p + j + 1], acc[j][p]);
            }
        } else {
            const float* xw0 = &sx[buf][0][xwoff];
            const float* yb0 = &sy[buf][0][0];
            #pragma unroll
            for (int cc = 0; cc < CPB; cc++) {
                const float* xw = xw0 + cc * XSLAB;
                float4 xa = *reinterpret_cast<const float4*>(xw);
                float4 xb = *reinterpret_cast<const float4*>(xw + 4);
                sxxw[0] = fmaf(xa.x, xa.x, sxxw[0]);
                sxxw[1] = fmaf(xa.y, xa.y, sxxw[1]);
                sxxw[2] = fmaf(xa.z, xa.z, sxxw[2]);
                sxxw[3] = fmaf(xa.w, xa.w, sxxw[3]);
                sxxw[4] = fmaf(xb.x, xb.x, sxxw[4]);
                sxxw[5] = fmaf(xb.y, xb.y, sxxw[5]);
                sxxw[6] = fmaf(xb.z, xb.z, sxxw[6]);
                sxxw[7] = fmaf(xb.w, xb.w, sxxw[7]);
                const float2* slab2 = reinterpret_cast<const float2*>(yb0 + cc * SLAB);
                #pragma unroll
                for (int k = 0; k < W7SLOT; k++) {
                    if (sv & (1u << k)) {
                        float2 v = slab2[soff[k]];
                        syyA[k] = fmaf(v.x, v.x, syyA[k]);
                        syyB[k] = fmaf(v.y, v.y, syyB[k]);
                    }
                }
            }
        }

        cp_wait0();
        __syncthreads();
    }

    // ================= epilogue: normalize =================
    if (!comp) {
        #pragma unroll
        for (int k = 0; k < W7SLOT; k++)
            if (sv & (1u << k))
                reinterpret_cast<float2*>(&sy[0][0][0])[soff[k]] =
                    make_float2(syyA[k], syyB[k]);
        float* xw = &sx[0][0][xwoff];
        #pragma unroll
        for (int p = 0; p < 8; p++)
            xw[p] = 1.0f / fmaxf(sqrtf(sxxw[p]), EPSF);
    }
    __syncthreads();

    if (comp) {
        const float* xr = &sx[0][0][ty * XROW + tx * 8];
        float4 ia = *reinterpret_cast<const float4*>(xr);
        float4 ib = *reinterpret_cast<const float4*>(xr + 4);
        float invx[8] = {ia.x, ia.y, ia.z, ia.w, ib.x, ib.y, ib.z, ib.w};

        const float* row = &sy[0][0][(ty + grp) * SMW + tx * 8];
        float inr[15];
        #pragma unroll
        for (int t = 1; t <= 14; t++)
            inr[t] = 1.0f / fmaxf(sqrtf(row[t]), EPSF);

        float* op = out + ((size_t)b * 49 + grp * 7) * PLANE
                        + (size_t)h * WW + w0 + tx * 8;
        #pragma unroll
        for (int j = 0; j < 7; j++) {
            float4 oa, ob;
            oa.x = acc[j][0] * invx[0] * inr[j + 1];
            oa.y = acc[j][1] * invx[1] * inr[j + 2];
            oa.z = acc[j][2] * invx[2] * inr[j + 3];
            oa.w = acc[j][3] * invx[3] * inr[j + 4];
            ob.x = acc[j][4] * invx[4] * inr[j + 5];
            ob.y = acc[j][5] * invx[5] * inr[j + 6];
            ob.z = acc[j][6] * invx[6] * inr[j + 7];
            ob.w = acc[j][7] * invx[7] * inr[j + 8];
            *reinterpret_cast<float4*>(op + (size_t)j * PLANE)     = oa;
            *reinterpret_cast<float4*>(op + (size_t)j * PLANE + 4) = ob;
        }
    }
}

extern "C" void kernel_launch(void* const* d_in, const int* in_sizes, int n_in,
                              void* d_out, int out_size) {
    const float* x = (const float*)d_in[0];
    const float* y = (const float*)d_in[1];
    float* out = (float*)d_out;
    int B = in_sizes[0] / (CCH * HH * WW);   // = 4
    dim3 grid(WW / TW, HH / TH, B);
    corr_kernel<<<grid, NTHREADS>>>(x, y, out);
}

// round 12
// speedup vs baseline: 1.2208x; 1.2208x over previous
#include <cuda_runtime.h>
#include <cstdint>

#define CCH 256
#define HH 256
#define WW 256
#define PLANE (HH * WW)
#define TH 4
#define TW 32
#define HALO_ROWS 10              // TH + 6
#define HALO_W2 20                // staged float2 per row (40 floats)
#define HALO_N2 (HALO_ROWS * HALO_W2)  // 200 float2 per channel slab
#define SMW 44                    // y slab row stride in floats (conflict-free padding)
#define SMW2 (SMW / 2)            // 22 float2 stride
#define SLAB (HALO_ROWS * SMW)    // 440 floats per y slab
#define XROW 36                   // x slab row stride in floats (conflict-free padding)
#define XSLAB (TH * XROW)         // 144 floats per x slab
#define CPB 4                     // channels per barrier
#define NGRP (CCH / CPB)          // 64 groups
#define NSLOT 2                   // ceil(200 / 128) y staging slots per thread
#define NTHREADS 128
#define EPSF 1e-12f

__device__ __forceinline__ unsigned smem_u32(const void* p) {
    return (unsigned)__cvta_generic_to_shared(p);
}
__device__ __forceinline__ void cp_async8(unsigned dst, const void* src, unsigned sz) {
    asm volatile("cp.async.ca.shared.global [%0], [%1], 8, %2;\n"
                 :: "r"(dst), "l"(src), "r"(sz));
}
__device__ __forceinline__ void cp_async16(unsigned dst, const void* src) {
    asm volatile("cp.async.ca.shared.global [%0], [%1], 16;\n"
                 :: "r"(dst), "l"(src));
}
__device__ __forceinline__ void cp_commit() {
    asm volatile("cp.async.commit_group;\n");
}
__device__ __forceinline__ void cp_wait0() {
    asm volatile("cp.async.wait_group 0;\n");
}

__global__ __launch_bounds__(NTHREADS, 4)
void corr_kernel(const float* __restrict__ x,
                 const float* __restrict__ y,
                 float* __restrict__ out)
{
    __shared__ __align__(16) float sy[2][CPB][SLAB];
    __shared__ __align__(16) float sx[2][CPB][XSLAB];

    const int tid = threadIdx.x;
    const int tx  = tid & 3;          // 0..3, each owns 8 w-pixels
    const int ty  = (tid >> 2) & 3;   // 0..3
    const int grp = tid >> 4;         // 0..7: vertical offset index (7 = staging-only)
    const bool comp = (grp < 7);
    const int b   = blockIdx.z;
    const int h0  = blockIdx.y * TH;
    const int w0  = blockIdx.x * TW;
    const int h   = h0 + ty;

    // ---- y staging slots: halo gy in [h0-3, h0+6], gx in [w0-4, w0+35], even gx
    int      g2of[NSLOT];   // global float2 offset
    int      d2of[NSLOT];   // slab float2 offset (stride 22 float2 per row)
    unsigned ssz[NSLOT];
    bool     wr[NSLOT];
    #pragma unroll
    for (int k = 0; k < NSLOT; k++) {
        int li = tid + k * NTHREADS;
        int r  = li / HALO_W2;
        int c2 = li - r * HALO_W2;
        int gy = h0 - 3 + r;
        int gx = w0 - 4 + 2 * c2;
        wr[k]  = li < HALO_N2;
        bool v = wr[k] && gy >= 0 && gy < HH && gx >= 0 && gx < WW;
        g2of[k] = v ? (gy * (WW / 2) + (gx >> 1)) : 0;
        d2of[k] = r * SMW2 + c2;
        ssz[k]  = v ? 8u : 0u;
    }

    // ---- x staging: threads 0..31 stage one float4 per channel (4 rows x 8 quads)
    const bool xstage = (tid < 32);
    const unsigned xdst = (unsigned)((tid >> 3) * (XROW * 4) + (tid & 7) * 16);
    const float* xsrc = x + (((size_t)b * CCH) * HH + h0 + (tid >> 3)) * WW
                          + w0 + (tid & 7) * 4;
    const float2* yc = reinterpret_cast<const float2*>(y) +
        (size_t)b * CCH * (PLANE / 2);

    float acc[7][8];
    #pragma unroll
    for (int j = 0; j < 7; j++)
        #pragma unroll
        for (int p = 0; p < 8; p++)
            acc[j][p] = 0.f;

    float sxx[8];
    #pragma unroll
    for (int p = 0; p < 8; p++) sxx[p] = 0.f;
    float2 syy[NSLOT];
    #pragma unroll
    for (int k = 0; k < NSLOT; k++) syy[k] = make_float2(0.f, 0.f);

    // ---- prologue: stage group 0 (channels 0..3) into buffer 0
    #pragma unroll
    for (int cc = 0; cc < CPB; cc++) {
        unsigned dy = smem_u32(&sy[0][cc][0]);
        #pragma unroll
        for (int k = 0; k < NSLOT; k++)
            if (wr[k]) cp_async8(dy + (unsigned)d2of[k] * 8, yc + g2of[k], ssz[k]);
        yc += PLANE / 2;
        if (xstage)
            cp_async16(smem_u32(&sx[0][cc][0]) + xdst, xsrc + (size_t)cc * PLANE);
    }
    cp_commit();
    cp_wait0();
    __syncthreads();

    // ================= group loop: 64 iterations of 4 channels =================
    #pragma unroll 1
    for (int g = 0; g < NGRP; g++) {
        const int buf = g & 1;
        const bool pf = (g + 1 < NGRP);

        if (pf) {
            #pragma unroll
            for (int cc = 0; cc < CPB; cc++) {
                unsigned dy = smem_u32(&sy[buf ^ 1][cc][0]);
                #pragma unroll
                for (int k = 0; k < NSLOT; k++)
                    if (wr[k]) cp_async8(dy + (unsigned)d2of[k] * 8,
                                         yc + g2of[k], ssz[k]);
                yc += PLANE / 2;
                if (xstage)
                    cp_async16(smem_u32(&sx[buf ^ 1][cc][0]) + xdst,
                               xsrc + (size_t)((g + 1) * CPB + cc) * PLANE);
            }
            cp_commit();
        }

        // ---- compute 4 channels from current buffers (R7 body, remapped)
        #pragma unroll
        for (int cc = 0; cc < CPB; cc++) {
            if (comp) {
                const float* xr = &sx[buf][cc][ty * XROW + tx * 8];
                float4 xa = *reinterpret_cast<const float4*>(xr);
                float4 xb = *reinterpret_cast<const float4*>(xr + 4);
                float xv[8] = {xa.x, xa.y, xa.z, xa.w, xb.x, xb.y, xb.z, xb.w};
                #pragma unroll
                for (int p = 0; p < 8; p++)
                    sxx[p] = fmaf(xv[p], xv[p], sxx[p]);

                const float* row = &sy[buf][cc][(ty + grp) * SMW + tx * 8];
                float4 t0 = *reinterpret_cast<const float4*>(row);
                float4 t1 = *reinterpret_cast<const float4*>(row + 4);
                float4 t2 = *reinterpret_cast<const float4*>(row + 8);
                float4 t3 = *reinterpret_cast<const float4*>(row + 12);
                float yr[16] = {t0.x, t0.y, t0.z, t0.w, t1.x, t1.y, t1.z, t1.w,
                                t2.x, t2.y, t2.z, t2.w, t3.x, t3.y, t3.z, t3.w};
                #pragma unroll
                for (int j = 0; j < 7; j++)
                    #pragma unroll
                    for (int p = 0; p < 8; p++)
                        acc[j][p] = fmaf(xv[p], yr[p + j + 1], acc[j][p]);
            }

            // sum(y^2) readback of this thread's own staged slots (zeros where OOB)
            const float2* slab2 = reinterpret_cast<const float2*>(&sy[buf][cc][0]);
            #pragma unroll
            for (int k = 0; k < NSLOT; k++) {
                if (wr[k]) {
                    float2 v = slab2[d2of[k]];
                    syy[k].x = fmaf(v.x, v.x, syy[k].x);
                    syy[k].y = fmaf(v.y, v.y, syy[k].y);
                }
            }
        }

        cp_wait0();
        __syncthreads();
    }

    // ================= epilogue: normalize =================
    // publish per-halo-pixel sum(y^2) through slab (0,0)
    #pragma unroll
    for (int k = 0; k < NSLOT; k++)
        if (wr[k])
            reinterpret_cast<float2*>(&sy[0][0][0])[d2of[k]] = syy[k];
    __syncthreads();

    if (comp) {
        float invx[8];
        #pragma unroll
        for (int p = 0; p < 8; p++)
            invx[p] = 1.0f / fmaxf(sqrtf(sxx[p]), EPSF);

        const float* row = &sy[0][0][(ty + grp) * SMW + tx * 8];
        float inr[15];
        #pragma unroll
        for (int t = 1; t <= 14; t++)
            inr[t] = 1.0f / fmaxf(sqrtf(row[t]), EPSF);

        float* op = out + ((size_t)b * 49 + grp * 7) * PLANE
                        + (size_t)h * WW + w0 + tx * 8;
        #pragma unroll
        for (int j = 0; j < 7; j++) {
            float4 oa, ob;
            oa.x = acc[j][0] * invx[0] * inr[j + 1];
            oa.y = acc[j][1] * invx[1] * inr[j + 2];
            oa.z = acc[j][2] * invx[2] * inr[j + 3];
            oa.w = acc[j][3] * invx[3] * inr[j + 4];
            ob.x = acc[j][4] * invx[4] * inr[j + 5];
            ob.y = acc[j][5] * invx[5] * inr[j + 6];
            ob.z = acc[j][6] * invx[6] * inr[j + 7];
            ob.w = acc[j][7] * invx[7] * inr[j + 8];
            *reinterpret_cast<float4*>(op + (size_t)j * PLANE)     = oa;
            *reinterpret_cast<float4*>(op + (size_t)j * PLANE + 4) = ob;
        }
    }
}

extern "C" void kernel_launch(void* const* d_in, const int* in_sizes, int n_in,
                              void* d_out, int out_size) {
    const float* x = (const float*)d_in[0];
    const float* y = (const float*)d_in[1];
    float* out = (float*)d_out;
    int B = in_sizes[0] / (CCH * HH * WW);   // = 4
    dim3 grid(WW / TW, HH / TH, B);
    corr_kernel<<<grid, NTHREADS>>>(x, y, out);
}